// round 2
// baseline (speedup 1.0000x reference)
#include <cuda_runtime.h>
#include <cuda_bf16.h>

#define W_ 768
#define H_ 768
#define N_ 16
#define HW_ (H_ * W_)
#define BX 32
#define BY 16
#define NT (BX * BY)           /* 512 threads */
#define R_ 8                   /* halo radius: covers |flow| <= 7 guaranteed */
#define TW (BX + 2 * R_ + 1)   /* 49 */
#define TH (BY + 2 * R_ + 1)   /* 33 */
#define TSZ (TW * TH)          /* 1617 */
#define GX_ (W_ / BX)          /* 24  */
#define GY_ (H_ / BY)          /* 48  */
#define NBLK (GX_ * GY_ * N_)  /* 18432 */

__device__ float g_partials[NBLK];

// m1 = warp(GridXY, flo1) at integer pixel (ix,iy), closed form.
// flo1(ix,iy) comes from the smem tile when in range, else global fallback.
__device__ __forceinline__ float2 eval_m1(const float2* __restrict__ tile,
                                          int tx0, int ty0,
                                          const float* __restrict__ fxg,
                                          const float* __restrict__ fyg,
                                          int ix, int iy)
{
    float fxv, fyv;
    int lx = ix - tx0, ly = iy - ty0;
    if ((unsigned)lx < (unsigned)TW && (unsigned)ly < (unsigned)TH) {
        float2 t = tile[ly * TW + lx];
        fxv = t.x; fyv = t.y;
    } else {
        int idx = iy * W_ + ix;
        fxv = __ldg(fxg + idx);
        fyv = __ldg(fyg + idx);
    }
    float gx = (float)ix + fxv;
    float gy = (float)iy + fyv;
    float x0f = floorf(gx), y0f = floorf(gy);
    float wx1 = gx - x0f, wy1 = gy - y0f;
    float wx0 = 1.0f - wx1, wy0 = 1.0f - wy1;
    int x0 = (int)x0f, y0 = (int)y0f;
    bool vx0 = ((unsigned)x0 < (unsigned)W_);
    bool vx1 = ((unsigned)(x0 + 1) < (unsigned)W_);
    bool vy0 = ((unsigned)y0 < (unsigned)H_);
    bool vy1 = ((unsigned)(y0 + 1) < (unsigned)H_);
    float c00 = (vx0 && vy0) ? wx0 * wy0 : 0.0f;
    float c10 = (vx1 && vy0) ? wx1 * wy0 : 0.0f;
    float c01 = (vx0 && vy1) ? wx0 * wy1 : 0.0f;
    float c11 = (vx1 && vy1) ? wx1 * wy1 : 0.0f;
    float m = (c00 + c10) + (c01 + c11);
    const float invW = 1.0f / (float)(W_ - 1);
    const float invH = 1.0f / (float)(H_ - 1);
    float ox = ((c00 + c01) * (float)x0 + (c10 + c11) * (float)(x0 + 1)) * invW;
    float oy = ((c00 + c10) * (float)y0 + (c01 + c11) * (float)(y0 + 1)) * invH;
    float M = (m < 0.9999f) ? 0.0f : 1.0f;
    return make_float2(ox * M, oy * M);
}

// One direction: second warp (by f2) of analytic m1(f1).
__device__ __forceinline__ float dir_diff(const float2* __restrict__ tile1,
                                          int tx0, int ty0,
                                          const float* __restrict__ f1x,
                                          const float* __restrict__ f1y,
                                          float2 f2own,
                                          int px, int py, float Gx, float Gy)
{
    float gx = (float)px + f2own.x;
    float gy = (float)py + f2own.y;
    float x0f = floorf(gx), y0f = floorf(gy);
    float wx1 = gx - x0f, wy1 = gy - y0f;
    float wx0 = 1.0f - wx1, wy0 = 1.0f - wy1;
    int x0 = (int)x0f, y0 = (int)y0f;
    bool vx0 = ((unsigned)x0 < (unsigned)W_);
    bool vx1 = ((unsigned)(x0 + 1) < (unsigned)W_);
    bool vy0 = ((unsigned)y0 < (unsigned)H_);
    bool vy1 = ((unsigned)(y0 + 1) < (unsigned)H_);
    float w00 = wx0 * wy0, w10 = wx1 * wy0, w01 = wx0 * wy1, w11 = wx1 * wy1;

    float mask = 0.0f, mx = 0.0f, my = 0.0f;
    if (vx0 && vy0) {
        float2 v = eval_m1(tile1, tx0, ty0, f1x, f1y, x0, y0);
        mask += w00; mx += w00 * v.x; my += w00 * v.y;
    }
    if (vx1 && vy0) {
        float2 v = eval_m1(tile1, tx0, ty0, f1x, f1y, x0 + 1, y0);
        mask += w10; mx += w10 * v.x; my += w10 * v.y;
    }
    if (vx0 && vy1) {
        float2 v = eval_m1(tile1, tx0, ty0, f1x, f1y, x0, y0 + 1);
        mask += w01; mx += w01 * v.x; my += w01 * v.y;
    }
    if (vx1 && vy1) {
        float2 v = eval_m1(tile1, tx0, ty0, f1x, f1y, x0 + 1, y0 + 1);
        mask += w11; mx += w11 * v.x; my += w11 * v.y;
    }
    float M = (mask < 0.9999f) ? 0.0f : 1.0f;
    mx *= M; my *= M;
    float dx = Gx - mx, dy = Gy - my;
    return sqrtf(dx * dx + dy * dy + 1.0e-6f);  // EPS^2
}

__global__ __launch_bounds__(NT)
void fused_cycle_kernel(const float* __restrict__ A, const float* __restrict__ B)
{
    __shared__ float2 tA[TSZ];
    __shared__ float2 tB[TSZ];

    int n = blockIdx.z;
    const float* Ax = A + (size_t)n * 2 * HW_;
    const float* Ay = Ax + HW_;
    const float* Bx = B + (size_t)n * 2 * HW_;
    const float* By = Bx + HW_;

    int tx0 = blockIdx.x * BX - R_;
    int ty0 = blockIdx.y * BY - R_;
    int tid = threadIdx.y * BX + threadIdx.x;

    // Cooperative tile fill (channel-interleaved), coalesced along x.
    #pragma unroll
    for (int i = tid; i < TSZ; i += NT) {
        int ly = i / TW, lx = i - ly * TW;
        int gx = tx0 + lx, gy = ty0 + ly;
        if ((unsigned)gx < (unsigned)W_ && (unsigned)gy < (unsigned)H_) {
            int idx = gy * W_ + gx;
            tA[i] = make_float2(__ldg(Ax + idx), __ldg(Ay + idx));
            tB[i] = make_float2(__ldg(Bx + idx), __ldg(By + idx));
        }
    }
    __syncthreads();

    int px = blockIdx.x * BX + threadIdx.x;
    int py = blockIdx.y * BY + threadIdx.y;
    const float invW = 1.0f / (float)(W_ - 1);
    const float invH = 1.0f / (float)(H_ - 1);
    float Gx = (float)px * invW;
    float Gy = (float)py * invH;

    int lown = (threadIdx.y + R_) * TW + (threadIdx.x + R_);
    float2 aown = tA[lown];
    float2 bown = tB[lown];

    // ABA: f1=A (gather tile A), f2=B (own-pixel B). BAB: swapped.
    float s = dir_diff(tA, tx0, ty0, Ax, Ay, bown, px, py, Gx, Gy)
            + dir_diff(tB, tx0, ty0, Bx, By, aown, px, py, Gx, Gy);

    // Block reduction: 16 warps
    #pragma unroll
    for (int o = 16; o > 0; o >>= 1)
        s += __shfl_down_sync(0xffffffffu, s, o);
    __shared__ float shred[NT / 32];
    if ((tid & 31) == 0) shred[tid >> 5] = s;
    __syncthreads();
    if (tid < 16) {
        float v = shred[tid];
        #pragma unroll
        for (int o = 8; o > 0; o >>= 1)
            v += __shfl_down_sync(0x0000ffffu, v, o);
        if (tid == 0) {
            int bid = blockIdx.x + GX_ * (blockIdx.y + GY_ * blockIdx.z);
            g_partials[bid] = v;
        }
    }
}

__global__ __launch_bounds__(1024)
void final_reduce_kernel(float* __restrict__ out)
{
    int t = threadIdx.x;
    const float4* p4 = (const float4*)g_partials;  // NBLK % 4 == 0
    const int n4 = NBLK / 4;                        // 4608
    double s = 0.0;
    #pragma unroll 5
    for (int i = t; i < n4; i += 1024) {
        float4 v = p4[i];
        s += (double)((v.x + v.y) + (v.z + v.w));
    }
    #pragma unroll
    for (int o = 16; o > 0; o >>= 1)
        s += __shfl_down_sync(0xffffffffu, s, o);
    __shared__ double sh[32];
    if ((t & 31) == 0) sh[t >> 5] = s;
    __syncthreads();
    if (t < 32) {
        double v = sh[t];
        #pragma unroll
        for (int o = 16; o > 0; o >>= 1)
            v += __shfl_down_sync(0xffffffffu, v, o);
        if (t == 0)
            out[0] = (float)(v / ((double)N_ * (double)HW_));
    }
}

extern "C" void kernel_launch(void* const* d_in, const int* in_sizes, int n_in,
                              void* d_out, int out_size)
{
    const float* A = (const float*)d_in[0];  // UV_AtoB
    const float* B = (const float*)d_in[1];  // UV_BtoA
    dim3 block(BX, BY);
    dim3 grid(GX_, GY_, N_);
    fused_cycle_kernel<<<grid, block>>>(A, B);
    final_reduce_kernel<<<1, 1024>>>((float*)d_out);
}

// round 3
// speedup vs baseline: 1.2082x; 1.2082x over previous
#include <cuda_runtime.h>
#include <cuda_bf16.h>

#define W_ 768
#define H_ 768
#define N_ 16
#define HW_ (H_ * W_)
#define BX 32
#define BY 8
#define NT (BX * BY)
#define GX_ (W_ / BX)          /* 24  */
#define GY_ (H_ / BY)          /* 96  */
#define NBLK (GX_ * GY_ * N_)  /* 36864 */

__device__ float g_partials[NBLK];

// m1 = warp(GridXY, flo1) at integer pixel (ix,iy), given flo1(ix,iy) already
// loaded. Closed form: GridXY is linear so the masked bilinear sample needs
// only the local flow value.
__device__ __forceinline__ float2 m1_from(float fxv, float fyv, int ix, int iy)
{
    float gx = (float)ix + fxv;
    float gy = (float)iy + fyv;
    float x0f = floorf(gx), y0f = floorf(gy);
    float wx1 = gx - x0f, wy1 = gy - y0f;
    float wx0 = 1.0f - wx1, wy0 = 1.0f - wy1;
    int x0 = (int)x0f, y0 = (int)y0f;
    bool vx0 = ((unsigned)x0 < (unsigned)W_);
    bool vx1 = ((unsigned)(x0 + 1) < (unsigned)W_);
    bool vy0 = ((unsigned)y0 < (unsigned)H_);
    bool vy1 = ((unsigned)(y0 + 1) < (unsigned)H_);
    float c00 = (vx0 && vy0) ? wx0 * wy0 : 0.0f;
    float c10 = (vx1 && vy0) ? wx1 * wy0 : 0.0f;
    float c01 = (vx0 && vy1) ? wx0 * wy1 : 0.0f;
    float c11 = (vx1 && vy1) ? wx1 * wy1 : 0.0f;
    float m = (c00 + c10) + (c01 + c11);
    const float invW = 1.0f / (float)(W_ - 1);
    const float invH = 1.0f / (float)(H_ - 1);
    float ox = ((c00 + c01) * (float)x0 + (c10 + c11) * (float)(x0 + 1)) * invW;
    float oy = ((c00 + c10) * (float)y0 + (c01 + c11) * (float)(y0 + 1)) * invH;
    float M = (m < 0.9999f) ? 0.0f : 1.0f;
    return make_float2(ox * M, oy * M);
}

// One direction: second warp (by f2own) of analytic m1(f1). All 8 corner
// gathers are unconditional clamped loads (batched for MLP); validity only
// zeroes the bilinear weight, matching the reference's zeros-padding.
__device__ __forceinline__ float dir_diff(const float* __restrict__ f1x,
                                          const float* __restrict__ f1y,
                                          float f2ox, float f2oy,
                                          int px, int py, float Gx, float Gy)
{
    float gx = (float)px + f2ox;
    float gy = (float)py + f2oy;
    float x0f = floorf(gx), y0f = floorf(gy);
    float wx1 = gx - x0f, wy1 = gy - y0f;
    float wx0 = 1.0f - wx1, wy0 = 1.0f - wy1;
    int x0 = (int)x0f, y0 = (int)y0f;
    int x1 = x0 + 1,   y1 = y0 + 1;
    bool vx0 = ((unsigned)x0 < (unsigned)W_);
    bool vx1 = ((unsigned)x1 < (unsigned)W_);
    bool vy0 = ((unsigned)y0 < (unsigned)H_);
    bool vy1 = ((unsigned)y1 < (unsigned)H_);
    // clamped coords (always in range -> loads always legal)
    int xc0 = min(max(x0, 0), W_ - 1);
    int xc1 = min(max(x1, 0), W_ - 1);
    int yc0 = min(max(y0, 0), H_ - 1);
    int yc1 = min(max(y1, 0), H_ - 1);
    int b00 = yc0 * W_ + xc0;
    int b10 = yc0 * W_ + xc1;
    int b01 = yc1 * W_ + xc0;
    int b11 = yc1 * W_ + xc1;

    // Batch all 8 gathers (independent -> high MLP)
    float fx00 = __ldg(f1x + b00);
    float fx10 = __ldg(f1x + b10);
    float fx01 = __ldg(f1x + b01);
    float fx11 = __ldg(f1x + b11);
    float fy00 = __ldg(f1y + b00);
    float fy10 = __ldg(f1y + b10);
    float fy01 = __ldg(f1y + b01);
    float fy11 = __ldg(f1y + b11);

    float w00 = (vx0 && vy0) ? wx0 * wy0 : 0.0f;
    float w10 = (vx1 && vy0) ? wx1 * wy0 : 0.0f;
    float w01 = (vx0 && vy1) ? wx0 * wy1 : 0.0f;
    float w11 = (vx1 && vy1) ? wx1 * wy1 : 0.0f;

    float2 v00 = m1_from(fx00, fy00, x0, y0);
    float2 v10 = m1_from(fx10, fy10, x1, y0);
    float2 v01 = m1_from(fx01, fy01, x0, y1);
    float2 v11 = m1_from(fx11, fy11, x1, y1);

    float mask = ((w00 + w10) + (w01 + w11));
    float mx = ((w00 * v00.x + w10 * v10.x) + (w01 * v01.x + w11 * v11.x));
    float my = ((w00 * v00.y + w10 * v10.y) + (w01 * v01.y + w11 * v11.y));

    float M = (mask < 0.9999f) ? 0.0f : 1.0f;
    mx *= M; my *= M;
    float dx = Gx - mx, dy = Gy - my;
    return sqrtf(dx * dx + dy * dy + 1.0e-6f);  // EPS^2 = 1e-6
}

__global__ __launch_bounds__(NT)
void fused_cycle_kernel(const float* __restrict__ A, const float* __restrict__ B)
{
    int px = blockIdx.x * BX + threadIdx.x;
    int py = blockIdx.y * BY + threadIdx.y;
    int n  = blockIdx.z;

    const float* Ax = A + (size_t)n * 2 * HW_;
    const float* Ay = Ax + HW_;
    const float* Bx = B + (size_t)n * 2 * HW_;
    const float* By = Bx + HW_;

    // Own-pixel flow loads up front (4 independent, fully coalesced)
    int idx = py * W_ + px;
    float aox = __ldg(Ax + idx);
    float aoy = __ldg(Ay + idx);
    float box = __ldg(Bx + idx);
    float boy = __ldg(By + idx);

    const float invW = 1.0f / (float)(W_ - 1);
    const float invH = 1.0f / (float)(H_ - 1);
    float Gx = (float)px * invW;
    float Gy = (float)py * invH;

    // ABA: f1=A gathered at corners of p+B(p). BAB: swapped.
    float s = dir_diff(Ax, Ay, box, boy, px, py, Gx, Gy)
            + dir_diff(Bx, By, aox, aoy, px, py, Gx, Gy);

    // Block reduction (256 threads = 8 warps)
    int tid = threadIdx.y * BX + threadIdx.x;
    #pragma unroll
    for (int o = 16; o > 0; o >>= 1)
        s += __shfl_down_sync(0xffffffffu, s, o);
    __shared__ float sh[NT / 32];
    if ((tid & 31) == 0) sh[tid >> 5] = s;
    __syncthreads();
    if (tid < 8) {
        float v = sh[tid];
        #pragma unroll
        for (int o = 4; o > 0; o >>= 1)
            v += __shfl_down_sync(0x000000ffu, v, o);
        if (tid == 0) {
            int bid = blockIdx.x + GX_ * (blockIdx.y + GY_ * blockIdx.z);
            g_partials[bid] = v;
        }
    }
}

__global__ __launch_bounds__(1024)
void final_reduce_kernel(float* __restrict__ out)
{
    int t = threadIdx.x;
    const float4* p4 = (const float4*)g_partials;  // NBLK % 4 == 0
    const int n4 = NBLK / 4;                        // 9216
    double s = 0.0;
    #pragma unroll 5
    for (int i = t; i < n4; i += 1024) {
        float4 v = p4[i];
        s += (double)((v.x + v.y) + (v.z + v.w));
    }
    #pragma unroll
    for (int o = 16; o > 0; o >>= 1)
        s += __shfl_down_sync(0xffffffffu, s, o);
    __shared__ double sh[32];
    if ((t & 31) == 0) sh[t >> 5] = s;
    __syncthreads();
    if (t < 32) {
        double v = sh[t];
        #pragma unroll
        for (int o = 16; o > 0; o >>= 1)
            v += __shfl_down_sync(0xffffffffu, v, o);
        if (t == 0)
            out[0] = (float)(v / ((double)N_ * (double)HW_));
    }
}

extern "C" void kernel_launch(void* const* d_in, const int* in_sizes, int n_in,
                              void* d_out, int out_size)
{
    const float* A = (const float*)d_in[0];  // UV_AtoB
    const float* B = (const float*)d_in[1];  // UV_BtoA
    dim3 block(BX, BY);
    dim3 grid(GX_, GY_, N_);
    fused_cycle_kernel<<<grid, block>>>(A, B);
    final_reduce_kernel<<<1, 1024>>>((float*)d_out);
}